// round 6
// baseline (speedup 1.0000x reference)
#include <cuda_runtime.h>

// Flow-warp bilinear, direct gather, 2 output rows per thread, persistent
// grid-stride with grid sized to exactly one resident wave (148 SMs x 8 CTAs)
// to eliminate wave-quantization tail.
// out[b,c,y,x] = bilerp(src[b,c], clamp(y+flow[b,0,y,x]), clamp(x+flow[b,1,y,x]))
// B=8, C=16, H=W=512.

#define B_ 8
#define C_ 16
#define H_ 512
#define W_ 512
#define HW_ (H_ * W_)
#define CHW_ (C_ * HW_)

#define NBLK_ 1184                    // 148 SMs * 8 CTAs (32 regs, 256 thr)
#define TOTAL_ (B_ * (H_ / 2) * W_)   // 1,048,576 virtual threads (2 rows each)
#define STRIDE_ (NBLK_ * 256)

__global__ void __launch_bounds__(256, 8) warp_gather_ps_kernel(
    const float* __restrict__ src,
    const float* __restrict__ flow,
    float* __restrict__ out)
{
    for (int vid = blockIdx.x * 256 + threadIdx.x; vid < TOTAL_; vid += STRIDE_) {
        int x  = vid & (W_ - 1);
        int ry = (vid >> 9) & 255;
        int b  = vid >> 17;
        int y  = ry * 2;

        const float* __restrict__ fby = flow + b * 2 * HW_;
        const float* __restrict__ fbx = fby + HW_;

        int   g00[2];
        float wxv[2], wyv[2];

#pragma unroll
        for (int k = 0; k < 2; ++k) {
            int yy = y + k;
            int fo = yy * W_ + x;
            float fy = __ldg(fby + fo);
            float fx = __ldg(fbx + fo);
            // reference's normalize->unnormalize cancels exactly
            float py = fminf(fmaxf((float)yy + fy, 0.0f), (float)(H_ - 1));
            float px = fminf(fmaxf((float)x  + fx, 0.0f), (float)(W_ - 1));
            float y0f = floorf(py);
            float x0f = floorf(px);
            int y0 = min((int)y0f, H_ - 2);   // edge: weight becomes exactly 1
            int x0 = min((int)x0f, W_ - 2);
            wyv[k] = py - (float)y0;
            wxv[k] = px - (float)x0;
            g00[k] = (y0 << 9) + x0;
        }

        const float* __restrict__ sb = src + b * CHW_;
        float* __restrict__ ob = out + b * CHW_ + y * W_ + x;

        const int gA = g00[0];
        const int gB = g00[1];

#pragma unroll
        for (int c = 0; c < C_; ++c) {
            const float* __restrict__ sc = sb + c * HW_;
            float a00 = __ldg(sc + gA);
            float a01 = __ldg(sc + gA + 1);
            float a10 = __ldg(sc + gA + W_);
            float a11 = __ldg(sc + gA + W_ + 1);
            float b00 = __ldg(sc + gB);
            float b01 = __ldg(sc + gB + 1);
            float b10 = __ldg(sc + gB + W_);
            float b11 = __ldg(sc + gB + W_ + 1);

            float atop = fmaf(wxv[0], a01 - a00, a00);
            float abot = fmaf(wxv[0], a11 - a10, a10);
            float btop = fmaf(wxv[1], b01 - b00, b00);
            float bbot = fmaf(wxv[1], b11 - b10, b10);

            float* __restrict__ oc = ob + c * HW_;
            oc[0]  = fmaf(wyv[0], abot - atop, atop);
            oc[W_] = fmaf(wyv[1], bbot - btop, btop);
        }
    }
}

extern "C" void kernel_launch(void* const* d_in, const int* in_sizes, int n_in,
                              void* d_out, int out_size)
{
    const float* src  = (const float*)d_in[0];
    const float* flow = (const float*)d_in[1];
    float* out        = (float*)d_out;

    warp_gather_ps_kernel<<<NBLK_, 256>>>(src, flow, out);
}